// round 16
// baseline (speedup 1.0000x reference)
#include <cuda_runtime.h>
#include <cuda_fp16.h>
#include <cstdint>
#include <math.h>

#define NB   64
#define NTT  512
#define NE   1024
#define ND   1024
#define NF   2048
#define NM   (NTT*NB)
#define NTILES 8          // 2048 / 256 N-tiles

// ---------------- scratch ----------------
__device__ float g_hproj[NB * NF];
__device__ float g_obuf[NB * ND];
__device__ float g_spart[NM * NTILES];
__device__ float g_weights[NB * NTT];
__device__ __half g_ench[NM * NE];   // enc as fp16 [32768 x 1024]
__device__ __half g_wah[NF * NE];    // Wa[:,1024:] as fp16 [2048 x 1024]

// ---------------- helpers ----------------
__device__ __forceinline__ uint32_t smem_u32(const void* p) {
    uint32_t a;
    asm("{ .reg .u64 t; cvta.to.shared.u64 t, %1; cvt.u32.u64 %0, t; }" : "=r"(a) : "l"(p));
    return a;
}
// FMA/ALU-only tanh (exact path, used for final output). abs err ~2e-7.
__device__ __forceinline__ float tanh_fma(float x) {
    float t = x * 2.885390081777927f;
    t = fminf(fmaxf(t, -30.f), 30.f);
    const float fi = t + 12582912.f;
    const int   ii = __float_as_int(fi) - 0x4B400000;
    const float r  = t - (fi - 12582912.f);
    float p = 1.5403530393381609e-4f;
    p = fmaf(p, r, 1.3333558146428443e-3f);
    p = fmaf(p, r, 9.6181298421260660e-3f);
    p = fmaf(p, r, 5.5504108664821580e-2f);
    p = fmaf(p, r, 2.4022650695910071e-1f);
    p = fmaf(p, r, 6.9314718055994531e-1f);
    p = fmaf(p, r, 1.0f);
    const float E = __int_as_float(__float_as_int(p) + (ii << 23));
    const float D = E + 1.0f;
    float y = __int_as_float(0x7EF311C3 - __float_as_int(D));
    y = y * fmaf(-D, y, 2.0f);
    y = y * fmaf(-D, y, 2.0f);
    y = y * fmaf(-D, y, 2.0f);
    return fmaf(-2.0f, y, 1.0f);
}
__device__ __forceinline__ float tanh_mufu(float x) {
    float r;
    asm("tanh.approx.f32 %0, %1;" : "=f"(r) : "f"(x));
    return r;
}
__device__ __forceinline__ void cpa16(uint32_t dst, const void* src) {
    asm volatile("cp.async.cg.shared.global [%0], [%1], 16;" :: "r"(dst), "l"(src));
}
__device__ __forceinline__ void cp_commit() {
    asm volatile("cp.async.commit_group;" ::: "memory");
}
template <int N>
__device__ __forceinline__ void cp_wait() {
    asm volatile("cp.async.wait_group %0;" :: "n"(N) : "memory");
}
__device__ __forceinline__ void mma16(float* c, const uint32_t* a, uint32_t b0, uint32_t b1) {
    asm volatile(
        "mma.sync.aligned.m16n8k16.row.col.f32.f16.f16.f32 "
        "{%0,%1,%2,%3}, {%4,%5,%6,%7}, {%8,%9}, {%0,%1,%2,%3};"
        : "+f"(c[0]), "+f"(c[1]), "+f"(c[2]), "+f"(c[3])
        : "r"(a[0]), "r"(a[1]), "r"(a[2]), "r"(a[3]), "r"(b0), "r"(b1));
}
__device__ __forceinline__ void ldsm4(uint32_t* r, uint32_t addr) {
    asm volatile("ldmatrix.sync.aligned.m8n8.x4.shared.b16 {%0,%1,%2,%3}, [%4];"
                 : "=r"(r[0]), "=r"(r[1]), "=r"(r[2]), "=r"(r[3]) : "r"(addr));
}

// =====================================================================
// K0: fused converts + init.
// enc->fp16, Wa[:,1024:]->fp16, hproj=ba, obuf=bc, applied=0.
// All segments are disjoint elementwise float4 work.
// =====================================================================
#define ENC4 (NM * NE / 4)          // 8388608
#define WA4  (NF * NE / 4)          // 524288
#define HP4  (NB * NF / 4)          // 32768
#define OB4  (NB * ND / 4)          // 16384
#define AP4  (NB * NE / 4)          // 16384
#define INIT_TOTAL (ENC4 + WA4 + HP4 + OB4 + AP4)
__global__ void conv_init_kernel(const float* __restrict__ enc,
                                 const float* __restrict__ Wa,
                                 const float* __restrict__ ba,
                                 const float* __restrict__ bc,
                                 float* __restrict__ applied)
{
    const int i = blockIdx.x * blockDim.x + threadIdx.x;
    if (i < ENC4) {
        const float4 v = ((const float4*)enc)[i];
        const __half2 h0 = __floats2half2_rn(v.x, v.y);
        const __half2 h1 = __floats2half2_rn(v.z, v.w);
        ((uint2*)g_ench)[i] = make_uint2(*(const uint32_t*)&h0, *(const uint32_t*)&h1);
    } else if (i < ENC4 + WA4) {
        const int j = i - ENC4;
        const int n = j >> 8, k4 = j & 255;
        const float4 v = *(const float4*)(Wa + (size_t)n * 2048 + 1024 + k4 * 4);
        const __half2 h0 = __floats2half2_rn(v.x, v.y);
        const __half2 h1 = __floats2half2_rn(v.z, v.w);
        ((uint2*)g_wah)[j] = make_uint2(*(const uint32_t*)&h0, *(const uint32_t*)&h1);
    } else {
        int j = i - ENC4 - WA4;
        if (j < HP4) {
            ((float4*)g_hproj)[j] = ((const float4*)ba)[j & (NF / 4 - 1)];
        } else if (j < HP4 + OB4) {
            const int k = j - HP4;
            ((float4*)g_obuf)[k] = ((const float4*)bc)[k & (ND / 4 - 1)];
        } else if (j < HP4 + OB4 + AP4) {
            const int k = j - HP4 - OB4;
            ((float4*)applied)[k] = make_float4(0.f, 0.f, 0.f, 0.f);
        }
    }
}

// =====================================================================
// K2: fp16 m16n8k16 fused scores (frozen best-measured config).
// CTA 128x256xK64, 512 threads, 16 warps (4x4) of 32x64, 4-stage
// cp.async, ldmatrix fragments. grid (8 n-tiles, 256 m-tiles).
// =====================================================================
#define STAGES   4
#define A_BY     16384                // 128 rows x 128 B
#define B_BY     32768                // 256 rows x 128 B
#define ST_BY    (A_BY + B_BY)        // 48 KB / stage
#define SMEM_BYTES (STAGES * ST_BY)   // 192 KB
#define NCH      16                   // 1024 / 64

__global__ __launch_bounds__(512, 1)
void fused_scores_tc(const float* __restrict__ w2)
{
    extern __shared__ __align__(16) char sm[];
    const uint32_t sbase = smem_u32(sm);
    const int tid  = threadIdx.x;
    const int lane = tid & 31;
    const int wid  = tid >> 5;
    const int wm   = wid >> 2;    // 0..3  (32 rows each)
    const int wn   = wid & 3;     // 0..3  (64 cols each)
    const int n0 = blockIdx.x * 256;
    const int m0 = blockIdx.y * 128;

    // staging: A 2 cpa/thread, B 4 cpa/thread
    const int arow = tid >> 2;            // 0..127
    const int ag0  = (tid & 3) * 2;
    const int ar7  = arow & 7;
    const int brow = tid >> 1;            // 0..255
    const int bg0  = (tid & 1) * 4;
    const int br7  = brow & 7;
    const __half* gA = g_ench + (size_t)(m0 + arow) * 1024 + ag0 * 8;
    const __half* gB = g_wah  + (size_t)(n0 + brow) * 1024 + bg0 * 8;
    const uint32_t dA = sbase + arow * 128;
    const uint32_t dB = sbase + A_BY + brow * 128;

    // ldmatrix per-lane geometry
    const int i7 = lane & 7;
    const int q  = lane >> 3;
    const int aGq = q >> 1;
    const uint32_t aRowOff = (uint32_t)(wm * 32 + (q & 1) * 8 + i7) * 128;
    const int bGq = q & 1;
    const uint32_t bRowOff = (uint32_t)(wn * 64 + (q >> 1) * 8 + i7) * 128;

    float acc[2][8][4];
#pragma unroll
    for (int i = 0; i < 2; i++)
#pragma unroll
        for (int j = 0; j < 8; j++)
#pragma unroll
            for (int r = 0; r < 4; r++) acc[i][j][r] = 0.f;

    auto issue = [&](int s, int ch) {
        const uint32_t off = s * ST_BY;
        const __half* pa = gA + ch * 64;
        const __half* pb = gB + ch * 64;
#pragma unroll
        for (int i = 0; i < 2; i++)
            cpa16(dA + off + (((ag0 + i) ^ ar7) << 4), pa + i * 8);
#pragma unroll
        for (int i = 0; i < 4; i++)
            cpa16(dB + off + (((bg0 + i) ^ br7) << 4), pb + i * 8);
        cp_commit();
    };

    issue(0, 0); issue(1, 1); issue(2, 2);

#pragma unroll 1
    for (int ch = 0; ch < NCH; ch++) {
        if (ch <= NCH - 3)      cp_wait<2>();
        else if (ch == NCH - 2) cp_wait<1>();
        else                    cp_wait<0>();
        __syncthreads();
        if (ch + 3 < NCH) issue((ch + 3) & 3, ch + 3);

        const uint32_t sA = sbase + (ch & 3) * ST_BY;
        const uint32_t sB = sA + A_BY;

#pragma unroll
        for (int ks = 0; ks < 4; ks++) {
            const uint32_t gA_off = (uint32_t)(((2 * ks + aGq) ^ i7) << 4);
            const uint32_t gB_off = (uint32_t)(((2 * ks + bGq) ^ i7) << 4);
            uint32_t af[2][4];
            ldsm4(af[0], sA + aRowOff + gA_off);
            ldsm4(af[1], sA + aRowOff + 16 * 128 + gA_off);
            uint32_t bf[4][4];
#pragma unroll
            for (int p = 0; p < 4; p++)
                ldsm4(bf[p], sB + bRowOff + (uint32_t)(p * 16 * 128) + gB_off);
#pragma unroll
            for (int mt = 0; mt < 2; mt++)
#pragma unroll
                for (int p = 0; p < 4; p++) {
                    mma16(acc[mt][2 * p],     af[mt], bf[p][0], bf[p][1]);
                    mma16(acc[mt][2 * p + 1], af[mt], bf[p][2], bf[p][3]);
                }
        }
    }

    __syncthreads();   // protect smem reuse

    // stage hproj [64 x 256] (stride 260) + w2 + reduce buffer
    float* hp_s = (float*)sm;
    float* w2_s = hp_s + 64 * 260;
    float* red  = w2_s + 256;
    for (int i = tid; i < 64 * 256; i += 512) {
        const int b = i >> 8, c = i & 255;
        hp_s[b * 260 + c] = g_hproj[(size_t)b * 2048 + n0 + c];
    }
    if (tid < 256) w2_s[tid] = w2[n0 + tid];
    __syncthreads();

    const int gr = lane >> 2;
    const int wd = lane & 3;
    const int cb = wd * 2;
#pragma unroll
    for (int mt = 0; mt < 2; mt++) {
        const int r1 = wm * 32 + mt * 16 + gr;
        const int r2 = r1 + 8;
        float s1 = 0.f, s2 = 0.f;
#pragma unroll
        for (int nt = 0; nt < 8; nt++) {
            const int col = wn * 64 + nt * 8 + cb;
            const float w0 = w2_s[col], w1 = w2_s[col + 1];
            const float h10 = hp_s[(r1 & 63) * 260 + col], h11 = hp_s[(r1 & 63) * 260 + col + 1];
            const float h20 = hp_s[(r2 & 63) * 260 + col], h21 = hp_s[(r2 & 63) * 260 + col + 1];
            s1 = fmaf(tanh_mufu(acc[mt][nt][0] + h10), w0, s1);
            s1 = fmaf(tanh_mufu(acc[mt][nt][1] + h11), w1, s1);
            s2 = fmaf(tanh_mufu(acc[mt][nt][2] + h20), w0, s2);
            s2 = fmaf(tanh_mufu(acc[mt][nt][3] + h21), w1, s2);
        }
        s1 += __shfl_down_sync(0xffffffffu, s1, 2, 4);
        s1 += __shfl_down_sync(0xffffffffu, s1, 1, 4);
        s2 += __shfl_down_sync(0xffffffffu, s2, 2, 4);
        s2 += __shfl_down_sync(0xffffffffu, s2, 1, 4);
        if (wd == 0) {
            red[r1 * 4 + wn] = s1;
            red[r2 * 4 + wn] = s2;
        }
    }
    __syncthreads();
    if (tid < 128) {
        const float v = red[tid * 4] + red[tid * 4 + 1] + red[tid * 4 + 2] + red[tid * 4 + 3];
        g_spart[(size_t)(m0 + tid) * NTILES + blockIdx.x] = v;
    }
}

// =====================================================================
// Split-K small GEMM with atomic accumulation (K1, K5).
// Acc target must be pre-initialized with the bias.
// =====================================================================
__global__ void split_gemm_atomic(const float* __restrict__ A,
                                  const float* __restrict__ A2, int ksplit, int lda,
                                  const float* __restrict__ Bm, int ldb,
                                  float* __restrict__ Acc, int ldc, int KS)
{
    __shared__ float As[16][33];
    __shared__ float Bs[16][33];
    const int tid = threadIdx.x;
    const int tx = tid & 15, ty = tid >> 4;
    const int m0 = blockIdx.y * 32, n0 = blockIdx.x * 32;
    const int kbeg = blockIdx.z * KS;
    float acc00 = 0.f, acc01 = 0.f, acc10 = 0.f, acc11 = 0.f;

    for (int k0 = kbeg; k0 < kbeg + KS; k0 += 16) {
        for (int i = tid; i < 32 * 16; i += 256) {
            const int r = i >> 4, c = i & 15;
            const int m = m0 + r, k = k0 + c;
            As[c][r] = (k < ksplit) ? A[(size_t)m * lda + k]
                                    : A2[(size_t)m * lda + (k - ksplit)];
            Bs[c][r] = Bm[(size_t)(n0 + r) * ldb + k];
        }
        __syncthreads();
#pragma unroll
        for (int k = 0; k < 16; k++) {
            const float a0 = As[k][ty * 2], a1 = As[k][ty * 2 + 1];
            const float b0 = Bs[k][tx * 2], b1 = Bs[k][tx * 2 + 1];
            acc00 = fmaf(a0, b0, acc00); acc01 = fmaf(a0, b1, acc01);
            acc10 = fmaf(a1, b0, acc10); acc11 = fmaf(a1, b1, acc11);
        }
        __syncthreads();
    }
    atomicAdd(Acc + (size_t)(m0 + ty * 2)     * ldc + n0 + tx * 2,     acc00);
    atomicAdd(Acc + (size_t)(m0 + ty * 2)     * ldc + n0 + tx * 2 + 1, acc01);
    atomicAdd(Acc + (size_t)(m0 + ty * 2 + 1) * ldc + n0 + tx * 2,     acc10);
    atomicAdd(Acc + (size_t)(m0 + ty * 2 + 1) * ldc + n0 + tx * 2 + 1, acc11);
}

__global__ void out_tanh_kernel(float* __restrict__ out)
{
    const int i = blockIdx.x * 256 + threadIdx.x;
    out[i] = tanh_fma(g_obuf[i]);
}

// =====================================================================
// K3: reduce partial scores + softmax
// =====================================================================
__global__ void softmax_kernel(const float* __restrict__ b2)
{
    const int b = blockIdx.x;
    const int tid = threadIdx.x;
    __shared__ float red[256];
    const float b2v = b2[0];

    float loc[2];
#pragma unroll
    for (int s = 0; s < 2; s++) {
        const int t = tid + s * 256;
        const float* p = g_spart + (size_t)(t * NB + b) * NTILES;
        float a = b2v;
#pragma unroll
        for (int n = 0; n < NTILES; n++) a += p[n];
        loc[s] = a;
    }
    red[tid] = fmaxf(loc[0], loc[1]);
    __syncthreads();
    for (int off = 128; off > 0; off >>= 1) {
        if (tid < off) red[tid] = fmaxf(red[tid], red[tid + off]);
        __syncthreads();
    }
    const float mx = red[0];
    __syncthreads();
    const float e0 = expf(loc[0] - mx);
    const float e1 = expf(loc[1] - mx);
    red[tid] = e0 + e1;
    __syncthreads();
    for (int off = 128; off > 0; off >>= 1) {
        if (tid < off) red[tid] += red[tid + off];
        __syncthreads();
    }
    const float inv = 1.f / red[0];
    g_weights[b * NTT + tid]       = e0 * inv;
    g_weights[b * NTT + tid + 256] = e1 * inv;
}

// =====================================================================
// K4: applied partials over 4 T-chunks (fp16 enc, half2 loads),
// atomic accumulation directly into d_out's applied half (pre-zeroed).
// =====================================================================
__global__ void applied_part_kernel(float* __restrict__ applied)
{
    const int b  = blockIdx.y;
    const int e2 = blockIdx.x * 256 + threadIdx.x;   // half2 index
    const int t0 = blockIdx.z * 128;
    __shared__ float w[128];
    if (threadIdx.x < 128) w[threadIdx.x] = g_weights[b * NTT + t0 + threadIdx.x];
    __syncthreads();
    const __half2* p = (const __half2*)(g_ench + ((size_t)t0 * NB + b) * 1024) + e2;
    float ax = 0.f, ay = 0.f;
#pragma unroll 8
    for (int t = 0; t < 128; t++) {
        const float2 v = __half22float2(p[(size_t)t * (NB * NE / 2)]);
        ax = fmaf(w[t], v.x, ax);
        ay = fmaf(w[t], v.y, ay);
    }
    float* dst = applied + b * 1024 + e2 * 2;
    atomicAdd(dst,     ax);
    atomicAdd(dst + 1, ay);
}

// =====================================================================
extern "C" void kernel_launch(void* const* d_in, const int* in_sizes, int n_in,
                              void* d_out, int out_size)
{
    const float* hidden = (const float*)d_in[0];
    const float* dec    = (const float*)d_in[1];
    const float* enc    = (const float*)d_in[2];
    const float* Wa     = (const float*)d_in[3];
    const float* ba     = (const float*)d_in[4];
    const float* w2     = (const float*)d_in[5];
    const float* b2     = (const float*)d_in[6];
    const float* Wc     = (const float*)d_in[7];
    const float* bc     = (const float*)d_in[8];

    float* out     = (float*)d_out;
    float* applied = out + NB * ND;

    cudaFuncSetAttribute(fused_scores_tc,
                         cudaFuncAttributeMaxDynamicSharedMemorySize, SMEM_BYTES);

    float* hproj; cudaGetSymbolAddress((void**)&hproj, g_hproj);
    float* obuf;  cudaGetSymbolAddress((void**)&obuf,  g_obuf);

    // K0: fused fp16 converts + accumulator init (hproj=ba, obuf=bc, applied=0)
    conv_init_kernel<<<(INIT_TOTAL + 255) / 256, 256>>>(enc, Wa, ba, bc, applied);

    // K1: h_proj += hidden @ Wa[:, :1024]^T  (split-K x4, atomic)
    split_gemm_atomic<<<dim3(NF / 32, NB / 32, 4), 256>>>(
        hidden, hidden, 1024, 1024, Wa, 2048, hproj, NF, 256);

    // K2: fp16 tensor-core fused scores -> g_spart
    fused_scores_tc<<<dim3(NTILES, NM / 128), 512, SMEM_BYTES>>>(w2);

    // K3: softmax -> g_weights
    softmax_kernel<<<NB, 256>>>(b2);

    // K4: applied += weights @ enc  (atomic into d_out second half)
    applied_part_kernel<<<dim3(NE / 512, NB, 4), 256>>>(applied);

    // K5: obuf += [dec|applied] @ Wc^T  (split-K x8, atomic)
    split_gemm_atomic<<<dim3(ND / 32, NB / 32, 8), 256>>>(
        dec, applied, 1024, 1024, Wc, 2048, obuf, ND, 256);

    // K6: out = tanh(obuf)
    out_tanh_kernel<<<(NB * ND) / 256, 256>>>(out);
}

// round 17
// speedup vs baseline: 1.0262x; 1.0262x over previous
#include <cuda_runtime.h>
#include <cuda_fp16.h>
#include <cstdint>
#include <math.h>

#define NB   64
#define NTT  512
#define NE   1024
#define ND   1024
#define NF   2048
#define NM   (NTT*NB)
#define NTILES 8          // 2048 / 256 N-tiles

// ---------------- scratch ----------------
__device__ float g_hproj[NB * NF];
__device__ float g_obuf[NB * ND];
__device__ float g_spart[NM * NTILES];
__device__ float g_weights[NB * NTT];
__device__ __half g_ench[NM * NE];   // enc as fp16 [32768 x 1024]
__device__ __half g_wah[NF * NE];    // Wa[:,1024:] as fp16 [2048 x 1024]

// ---------------- helpers ----------------
__device__ __forceinline__ uint32_t smem_u32(const void* p) {
    uint32_t a;
    asm("{ .reg .u64 t; cvta.to.shared.u64 t, %1; cvt.u32.u64 %0, t; }" : "=r"(a) : "l"(p));
    return a;
}
// FMA/ALU-only tanh (exact path, used for final output). abs err ~2e-7.
__device__ __forceinline__ float tanh_fma(float x) {
    float t = x * 2.885390081777927f;
    t = fminf(fmaxf(t, -30.f), 30.f);
    const float fi = t + 12582912.f;
    const int   ii = __float_as_int(fi) - 0x4B400000;
    const float r  = t - (fi - 12582912.f);
    float p = 1.5403530393381609e-4f;
    p = fmaf(p, r, 1.3333558146428443e-3f);
    p = fmaf(p, r, 9.6181298421260660e-3f);
    p = fmaf(p, r, 5.5504108664821580e-2f);
    p = fmaf(p, r, 2.4022650695910071e-1f);
    p = fmaf(p, r, 6.9314718055994531e-1f);
    p = fmaf(p, r, 1.0f);
    const float E = __int_as_float(__float_as_int(p) + (ii << 23));
    const float D = E + 1.0f;
    float y = __int_as_float(0x7EF311C3 - __float_as_int(D));
    y = y * fmaf(-D, y, 2.0f);
    y = y * fmaf(-D, y, 2.0f);
    y = y * fmaf(-D, y, 2.0f);
    return fmaf(-2.0f, y, 1.0f);
}
__device__ __forceinline__ float tanh_mufu(float x) {
    float r;
    asm("tanh.approx.f32 %0, %1;" : "=f"(r) : "f"(x));
    return r;
}
__device__ __forceinline__ void cpa16(uint32_t dst, const void* src) {
    asm volatile("cp.async.cg.shared.global [%0], [%1], 16;" :: "r"(dst), "l"(src));
}
__device__ __forceinline__ void cp_commit() {
    asm volatile("cp.async.commit_group;" ::: "memory");
}
template <int N>
__device__ __forceinline__ void cp_wait() {
    asm volatile("cp.async.wait_group %0;" :: "n"(N) : "memory");
}
__device__ __forceinline__ void mma16(float* c, const uint32_t* a, uint32_t b0, uint32_t b1) {
    asm volatile(
        "mma.sync.aligned.m16n8k16.row.col.f32.f16.f16.f32 "
        "{%0,%1,%2,%3}, {%4,%5,%6,%7}, {%8,%9}, {%0,%1,%2,%3};"
        : "+f"(c[0]), "+f"(c[1]), "+f"(c[2]), "+f"(c[3])
        : "r"(a[0]), "r"(a[1]), "r"(a[2]), "r"(a[3]), "r"(b0), "r"(b1));
}
__device__ __forceinline__ void ldsm4(uint32_t* r, uint32_t addr) {
    asm volatile("ldmatrix.sync.aligned.m8n8.x4.shared.b16 {%0,%1,%2,%3}, [%4];"
                 : "=r"(r[0]), "=r"(r[1]), "=r"(r[2]), "=r"(r[3]) : "r"(addr));
}

// =====================================================================
// K0: fused pre-kernel = K1 split-K GEMM (first 512 CTAs, runs in
// wave 1) + converts/init streaming behind it.
//   gemm part: hproj = ba + hidden @ Wa[:, :1024]^T (split-K x4,
//              atomic; bias added by z==0 block; hproj NOT pre-read)
//   conv part: enc->fp16, Wa[:,1024:]->fp16, obuf=bc, applied=0
// =====================================================================
#define ENC4 (NM * NE / 4)          // 8388608
#define WA4  (NF * NE / 4)          // 524288
#define OB4  (NB * ND / 4)          // 16384
#define AP4  (NB * NE / 4)          // 16384
#define CONV_TOTAL (ENC4 + WA4 + OB4 + AP4)
#define CONV_CTAS  ((CONV_TOTAL + 255) / 256)
#define K1_CTAS    (64 * 2 * 4)     // (NF/32) x (NB/32) x 4 splits
#define PRE_CTAS   (K1_CTAS + CONV_CTAS)

// zero-fill of g_hproj is replaced by bias-in-z0; nothing pre-reads hproj
__global__ void pre_kernel(const float* __restrict__ enc,
                           const float* __restrict__ Wa,
                           const float* __restrict__ ba,
                           const float* __restrict__ bc,
                           const float* __restrict__ hidden,
                           float* __restrict__ applied)
{
    __shared__ float As[16][33];
    __shared__ float Bs[16][33];
    const int tid = threadIdx.x;

    if (blockIdx.x < K1_CTAS) {
        // ---- K1: split-K GEMM, CTA idx -> (n-tile, m-tile, z) ----
        const int idx = blockIdx.x;
        const int bx = idx & 63;           // 0..63  n-tile
        const int by = (idx >> 6) & 1;     // 0..1   m-tile
        const int bz = idx >> 7;           // 0..3   k-split
        const int tx = tid & 15, ty = tid >> 4;
        const int m0 = by * 32, n0 = bx * 32;
        const int kbeg = bz * 256;
        float acc00 = 0.f, acc01 = 0.f, acc10 = 0.f, acc11 = 0.f;

        for (int k0 = kbeg; k0 < kbeg + 256; k0 += 16) {
            for (int i = tid; i < 32 * 16; i += 256) {
                const int r = i >> 4, c = i & 15;
                As[c][r] = hidden[(size_t)(m0 + r) * 1024 + k0 + c];
                Bs[c][r] = Wa[(size_t)(n0 + r) * 2048 + k0 + c];
            }
            __syncthreads();
#pragma unroll
            for (int k = 0; k < 16; k++) {
                const float a0 = As[k][ty * 2], a1 = As[k][ty * 2 + 1];
                const float b0 = Bs[k][tx * 2], b1 = Bs[k][tx * 2 + 1];
                acc00 = fmaf(a0, b0, acc00); acc01 = fmaf(a0, b1, acc01);
                acc10 = fmaf(a1, b0, acc10); acc11 = fmaf(a1, b1, acc11);
            }
            __syncthreads();
        }
        if (bz == 0) {   // bias added exactly once
            acc00 += ba[n0 + tx * 2];
            acc01 += ba[n0 + tx * 2 + 1];
            acc10 += ba[n0 + tx * 2];
            acc11 += ba[n0 + tx * 2 + 1];
        }
        atomicAdd(g_hproj + (size_t)(m0 + ty * 2)     * NF + n0 + tx * 2,     acc00);
        atomicAdd(g_hproj + (size_t)(m0 + ty * 2)     * NF + n0 + tx * 2 + 1, acc01);
        atomicAdd(g_hproj + (size_t)(m0 + ty * 2 + 1) * NF + n0 + tx * 2,     acc10);
        atomicAdd(g_hproj + (size_t)(m0 + ty * 2 + 1) * NF + n0 + tx * 2 + 1, acc11);
        return;
    }

    // ---- conv/init part ----
    const int i = (blockIdx.x - K1_CTAS) * 256 + tid;
    if (i < ENC4) {
        const float4 v = ((const float4*)enc)[i];
        const __half2 h0 = __floats2half2_rn(v.x, v.y);
        const __half2 h1 = __floats2half2_rn(v.z, v.w);
        ((uint2*)g_ench)[i] = make_uint2(*(const uint32_t*)&h0, *(const uint32_t*)&h1);
    } else if (i < ENC4 + WA4) {
        const int j = i - ENC4;
        const int n = j >> 8, k4 = j & 255;
        const float4 v = *(const float4*)(Wa + (size_t)n * 2048 + 1024 + k4 * 4);
        const __half2 h0 = __floats2half2_rn(v.x, v.y);
        const __half2 h1 = __floats2half2_rn(v.z, v.w);
        ((uint2*)g_wah)[j] = make_uint2(*(const uint32_t*)&h0, *(const uint32_t*)&h1);
    } else {
        int j = i - ENC4 - WA4;
        if (j < OB4) {
            ((float4*)g_obuf)[j] = ((const float4*)bc)[j & (ND / 4 - 1)];
        } else if (j < OB4 + AP4) {
            ((float4*)applied)[j - OB4] = make_float4(0.f, 0.f, 0.f, 0.f);
        }
    }
}

// =====================================================================
// hproj must start at 0 before pre_kernel atomics: tiny memset kernel
// (cheap, 512 CTAs of pure STG, overlaps nothing critical)
// =====================================================================
__global__ void hproj_zero_kernel()
{
    ((float4*)g_hproj)[blockIdx.x * 256 + threadIdx.x] = make_float4(0.f, 0.f, 0.f, 0.f);
}

// =====================================================================
// K2: fp16 m16n8k16 fused scores (frozen best-measured config).
// CTA 128x256xK64, 512 threads, 16 warps (4x4) of 32x64, 4-stage
// cp.async, ldmatrix fragments. grid (8 n-tiles, 256 m-tiles).
// =====================================================================
#define STAGES   4
#define A_BY     16384                // 128 rows x 128 B
#define B_BY     32768                // 256 rows x 128 B
#define ST_BY    (A_BY + B_BY)        // 48 KB / stage
#define SMEM_BYTES (STAGES * ST_BY)   // 192 KB
#define NCH      16                   // 1024 / 64

__global__ __launch_bounds__(512, 1)
void fused_scores_tc(const float* __restrict__ w2)
{
    extern __shared__ __align__(16) char sm[];
    const uint32_t sbase = smem_u32(sm);
    const int tid  = threadIdx.x;
    const int lane = tid & 31;
    const int wid  = tid >> 5;
    const int wm   = wid >> 2;    // 0..3  (32 rows each)
    const int wn   = wid & 3;     // 0..3  (64 cols each)
    const int n0 = blockIdx.x * 256;
    const int m0 = blockIdx.y * 128;

    // staging: A 2 cpa/thread, B 4 cpa/thread
    const int arow = tid >> 2;            // 0..127
    const int ag0  = (tid & 3) * 2;
    const int ar7  = arow & 7;
    const int brow = tid >> 1;            // 0..255
    const int bg0  = (tid & 1) * 4;
    const int br7  = brow & 7;
    const __half* gA = g_ench + (size_t)(m0 + arow) * 1024 + ag0 * 8;
    const __half* gB = g_wah  + (size_t)(n0 + brow) * 1024 + bg0 * 8;
    const uint32_t dA = sbase + arow * 128;
    const uint32_t dB = sbase + A_BY + brow * 128;

    // ldmatrix per-lane geometry
    const int i7 = lane & 7;
    const int q  = lane >> 3;
    const int aGq = q >> 1;
    const uint32_t aRowOff = (uint32_t)(wm * 32 + (q & 1) * 8 + i7) * 128;
    const int bGq = q & 1;
    const uint32_t bRowOff = (uint32_t)(wn * 64 + (q >> 1) * 8 + i7) * 128;

    float acc[2][8][4];
#pragma unroll
    for (int i = 0; i < 2; i++)
#pragma unroll
        for (int j = 0; j < 8; j++)
#pragma unroll
            for (int r = 0; r < 4; r++) acc[i][j][r] = 0.f;

    auto issue = [&](int s, int ch) {
        const uint32_t off = s * ST_BY;
        const __half* pa = gA + ch * 64;
        const __half* pb = gB + ch * 64;
#pragma unroll
        for (int i = 0; i < 2; i++)
            cpa16(dA + off + (((ag0 + i) ^ ar7) << 4), pa + i * 8);
#pragma unroll
        for (int i = 0; i < 4; i++)
            cpa16(dB + off + (((bg0 + i) ^ br7) << 4), pb + i * 8);
        cp_commit();
    };

    issue(0, 0); issue(1, 1); issue(2, 2);

#pragma unroll 1
    for (int ch = 0; ch < NCH; ch++) {
        if (ch <= NCH - 3)      cp_wait<2>();
        else if (ch == NCH - 2) cp_wait<1>();
        else                    cp_wait<0>();
        __syncthreads();
        if (ch + 3 < NCH) issue((ch + 3) & 3, ch + 3);

        const uint32_t sA = sbase + (ch & 3) * ST_BY;
        const uint32_t sB = sA + A_BY;

#pragma unroll
        for (int ks = 0; ks < 4; ks++) {
            const uint32_t gA_off = (uint32_t)(((2 * ks + aGq) ^ i7) << 4);
            const uint32_t gB_off = (uint32_t)(((2 * ks + bGq) ^ i7) << 4);
            uint32_t af[2][4];
            ldsm4(af[0], sA + aRowOff + gA_off);
            ldsm4(af[1], sA + aRowOff + 16 * 128 + gA_off);
            uint32_t bf[4][4];
#pragma unroll
            for (int p = 0; p < 4; p++)
                ldsm4(bf[p], sB + bRowOff + (uint32_t)(p * 16 * 128) + gB_off);
#pragma unroll
            for (int mt = 0; mt < 2; mt++)
#pragma unroll
                for (int p = 0; p < 4; p++) {
                    mma16(acc[mt][2 * p],     af[mt], bf[p][0], bf[p][1]);
                    mma16(acc[mt][2 * p + 1], af[mt], bf[p][2], bf[p][3]);
                }
        }
    }

    __syncthreads();   // protect smem reuse

    // stage hproj [64 x 256] (stride 260) + w2 + reduce buffer
    float* hp_s = (float*)sm;
    float* w2_s = hp_s + 64 * 260;
    float* red  = w2_s + 256;
    for (int i = tid; i < 64 * 256; i += 512) {
        const int b = i >> 8, c = i & 255;
        hp_s[b * 260 + c] = g_hproj[(size_t)b * 2048 + n0 + c];
    }
    if (tid < 256) w2_s[tid] = w2[n0 + tid];
    __syncthreads();

    const int gr = lane >> 2;
    const int wd = lane & 3;
    const int cb = wd * 2;
#pragma unroll
    for (int mt = 0; mt < 2; mt++) {
        const int r1 = wm * 32 + mt * 16 + gr;
        const int r2 = r1 + 8;
        float s1 = 0.f, s2 = 0.f;
#pragma unroll
        for (int nt = 0; nt < 8; nt++) {
            const int col = wn * 64 + nt * 8 + cb;
            const float w0 = w2_s[col], w1 = w2_s[col + 1];
            const float h10 = hp_s[(r1 & 63) * 260 + col], h11 = hp_s[(r1 & 63) * 260 + col + 1];
            const float h20 = hp_s[(r2 & 63) * 260 + col], h21 = hp_s[(r2 & 63) * 260 + col + 1];
            s1 = fmaf(tanh_mufu(acc[mt][nt][0] + h10), w0, s1);
            s1 = fmaf(tanh_mufu(acc[mt][nt][1] + h11), w1, s1);
            s2 = fmaf(tanh_mufu(acc[mt][nt][2] + h20), w0, s2);
            s2 = fmaf(tanh_mufu(acc[mt][nt][3] + h21), w1, s2);
        }
        s1 += __shfl_down_sync(0xffffffffu, s1, 2, 4);
        s1 += __shfl_down_sync(0xffffffffu, s1, 1, 4);
        s2 += __shfl_down_sync(0xffffffffu, s2, 2, 4);
        s2 += __shfl_down_sync(0xffffffffu, s2, 1, 4);
        if (wd == 0) {
            red[r1 * 4 + wn] = s1;
            red[r2 * 4 + wn] = s2;
        }
    }
    __syncthreads();
    if (tid < 128) {
        const float v = red[tid * 4] + red[tid * 4 + 1] + red[tid * 4 + 2] + red[tid * 4 + 3];
        g_spart[(size_t)(m0 + tid) * NTILES + blockIdx.x] = v;
    }
}

// =====================================================================
// Split-K small GEMM with atomic accumulation (K5).
// Acc target must be pre-initialized with the bias.
// =====================================================================
__global__ void split_gemm_atomic(const float* __restrict__ A,
                                  const float* __restrict__ A2, int ksplit, int lda,
                                  const float* __restrict__ Bm, int ldb,
                                  float* __restrict__ Acc, int ldc, int KS)
{
    __shared__ float As[16][33];
    __shared__ float Bs[16][33];
    const int tid = threadIdx.x;
    const int tx = tid & 15, ty = tid >> 4;
    const int m0 = blockIdx.y * 32, n0 = blockIdx.x * 32;
    const int kbeg = blockIdx.z * KS;
    float acc00 = 0.f, acc01 = 0.f, acc10 = 0.f, acc11 = 0.f;

    for (int k0 = kbeg; k0 < kbeg + KS; k0 += 16) {
        for (int i = tid; i < 32 * 16; i += 256) {
            const int r = i >> 4, c = i & 15;
            const int m = m0 + r, k = k0 + c;
            As[c][r] = (k < ksplit) ? A[(size_t)m * lda + k]
                                    : A2[(size_t)m * lda + (k - ksplit)];
            Bs[c][r] = Bm[(size_t)(n0 + r) * ldb + k];
        }
        __syncthreads();
#pragma unroll
        for (int k = 0; k < 16; k++) {
            const float a0 = As[k][ty * 2], a1 = As[k][ty * 2 + 1];
            const float b0 = Bs[k][tx * 2], b1 = Bs[k][tx * 2 + 1];
            acc00 = fmaf(a0, b0, acc00); acc01 = fmaf(a0, b1, acc01);
            acc10 = fmaf(a1, b0, acc10); acc11 = fmaf(a1, b1, acc11);
        }
        __syncthreads();
    }
    atomicAdd(Acc + (size_t)(m0 + ty * 2)     * ldc + n0 + tx * 2,     acc00);
    atomicAdd(Acc + (size_t)(m0 + ty * 2)     * ldc + n0 + tx * 2 + 1, acc01);
    atomicAdd(Acc + (size_t)(m0 + ty * 2 + 1) * ldc + n0 + tx * 2,     acc10);
    atomicAdd(Acc + (size_t)(m0 + ty * 2 + 1) * ldc + n0 + tx * 2 + 1, acc11);
}

__global__ void out_tanh_kernel(float* __restrict__ out)
{
    const int i = blockIdx.x * 256 + threadIdx.x;
    out[i] = tanh_fma(g_obuf[i]);
}

// =====================================================================
// K3: reduce partial scores + softmax
// =====================================================================
__global__ void softmax_kernel(const float* __restrict__ b2)
{
    const int b = blockIdx.x;
    const int tid = threadIdx.x;
    __shared__ float red[256];
    const float b2v = b2[0];

    float loc[2];
#pragma unroll
    for (int s = 0; s < 2; s++) {
        const int t = tid + s * 256;
        const float* p = g_spart + (size_t)(t * NB + b) * NTILES;
        float a = b2v;
#pragma unroll
        for (int n = 0; n < NTILES; n++) a += p[n];
        loc[s] = a;
    }
    red[tid] = fmaxf(loc[0], loc[1]);
    __syncthreads();
    for (int off = 128; off > 0; off >>= 1) {
        if (tid < off) red[tid] = fmaxf(red[tid], red[tid + off]);
        __syncthreads();
    }
    const float mx = red[0];
    __syncthreads();
    const float e0 = expf(loc[0] - mx);
    const float e1 = expf(loc[1] - mx);
    red[tid] = e0 + e1;
    __syncthreads();
    for (int off = 128; off > 0; off >>= 1) {
        if (tid < off) red[tid] += red[tid + off];
        __syncthreads();
    }
    const float inv = 1.f / red[0];
    g_weights[b * NTT + tid]       = e0 * inv;
    g_weights[b * NTT + tid + 256] = e1 * inv;
}

// =====================================================================
// K4: applied partials over 4 T-chunks (fp16 enc, half2 loads),
// atomic accumulation directly into d_out's applied half (pre-zeroed).
// =====================================================================
__global__ void applied_part_kernel(float* __restrict__ applied)
{
    const int b  = blockIdx.y;
    const int e2 = blockIdx.x * 256 + threadIdx.x;   // half2 index
    const int t0 = blockIdx.z * 128;
    __shared__ float w[128];
    if (threadIdx.x < 128) w[threadIdx.x] = g_weights[b * NTT + t0 + threadIdx.x];
    __syncthreads();
    const __half2* p = (const __half2*)(g_ench + ((size_t)t0 * NB + b) * 1024) + e2;
    float ax = 0.f, ay = 0.f;
#pragma unroll 8
    for (int t = 0; t < 128; t++) {
        const float2 v = __half22float2(p[(size_t)t * (NB * NE / 2)]);
        ax = fmaf(w[t], v.x, ax);
        ay = fmaf(w[t], v.y, ay);
    }
    float* dst = applied + b * 1024 + e2 * 2;
    atomicAdd(dst,     ax);
    atomicAdd(dst + 1, ay);
}

// =====================================================================
extern "C" void kernel_launch(void* const* d_in, const int* in_sizes, int n_in,
                              void* d_out, int out_size)
{
    const float* hidden = (const float*)d_in[0];
    const float* dec    = (const float*)d_in[1];
    const float* enc    = (const float*)d_in[2];
    const float* Wa     = (const float*)d_in[3];
    const float* ba     = (const float*)d_in[4];
    const float* w2     = (const float*)d_in[5];
    const float* b2     = (const float*)d_in[6];
    const float* Wc     = (const float*)d_in[7];
    const float* bc     = (const float*)d_in[8];

    float* out     = (float*)d_out;
    float* applied = out + NB * ND;

    cudaFuncSetAttribute(fused_scores_tc,
                         cudaFuncAttributeMaxDynamicSharedMemorySize, SMEM_BYTES);

    float* obuf; cudaGetSymbolAddress((void**)&obuf, g_obuf);

    // K-1: zero hproj (tiny; pre_kernel atomics accumulate onto it)
    hproj_zero_kernel<<<NB * NF / 4 / 256, 256>>>();

    // K0: fused K1-gemm (wave-1 CTAs) + converts + init
    pre_kernel<<<PRE_CTAS, 256>>>(enc, Wa, ba, bc, hidden, applied);

    // K2: fp16 tensor-core fused scores -> g_spart
    fused_scores_tc<<<dim3(NTILES, NM / 128), 512, SMEM_BYTES>>>(w2);

    // K3: softmax -> g_weights
    softmax_kernel<<<NB, 256>>>(b2);

    // K4: applied += weights @ enc  (atomic into d_out second half)
    applied_part_kernel<<<dim3(NE / 512, NB, 4), 256>>>(applied);

    // K5: obuf += [dec|applied] @ Wc^T  (split-K x8, atomic)
    split_gemm_atomic<<<dim3(ND / 32, NB / 32, 8), 256>>>(
        dec, applied, 1024, 1024, Wc, 2048, obuf, ND, 256);

    // K6: out = tanh(obuf)
    out_tanh_kernel<<<(NB * ND) / 256, 256>>>(out);
}